// round 4
// baseline (speedup 1.0000x reference)
#include <cuda_runtime.h>
#include <cuda_bf16.h>
#include <math.h>

// ---------------- problem constants ----------------
#define BB 2
#define SS 1024
#define DIM 4096
#define HH 32
#define QLORA 1536
#define KVLORA 512
#define NOPE 128
#define ROPE 64
#define VD 128
#define QK_HEAD 192          // NOPE + ROPE
#define MTOT (BB*SS)         // 2048
#define CDIM 576             // KVLORA + ROPE (combined score dim)
#define SCALE_F 0.07216878364870323f   // 192^-0.5

// ---------------- scratch (device globals; no allocation allowed) ----------------
__device__ __align__(16) float g_qa[MTOT * QLORA];           //  3.1M f
__device__ __align__(16) float g_q [MTOT * (HH*QK_HEAD)];    // 12.6M f
__device__ __align__(16) float g_Qc[MTOT * HH * CDIM];       // 37.7M f  [m][h][576] = [q_abs | roped q_pe]
__device__ __align__(16) float g_Kc[MTOT * CDIM];            //  1.2M f  [m][576]   = [rms(c_kv) | roped k_pe]
__device__ __align__(16) float g_sc[(long long)BB*HH*SS*SS]; // 67.1M f  [b][h][s][t]
__device__ __align__(16) float g_o1[MTOT * HH * KVLORA];     // 33.5M f  [m][h][512]
__device__ __align__(16) float g_o2[MTOT * DIM];             //  8.4M f  [m][h*128+d]

// ---------------- reductions ----------------
__device__ __forceinline__ float blockSum(float v) {
    __shared__ float sm[8];
    __syncthreads();
    int lane = threadIdx.x & 31, w = threadIdx.x >> 5;
    #pragma unroll
    for (int o = 16; o; o >>= 1) v += __shfl_xor_sync(0xffffffffu, v, o);
    if (lane == 0) sm[w] = v;
    __syncthreads();
    if (threadIdx.x < 8) {
        v = sm[threadIdx.x];
        #pragma unroll
        for (int o = 4; o; o >>= 1) v += __shfl_xor_sync(0xffu, v, o);
        if (lane == 0) sm[0] = v;
    }
    __syncthreads();
    return sm[0];
}

__device__ __forceinline__ float blockMax(float v) {
    __shared__ float sm2[8];
    __syncthreads();
    int lane = threadIdx.x & 31, w = threadIdx.x >> 5;
    #pragma unroll
    for (int o = 16; o; o >>= 1) v = fmaxf(v, __shfl_xor_sync(0xffffffffu, v, o));
    if (lane == 0) sm2[w] = v;
    __syncthreads();
    if (threadIdx.x < 8) {
        v = sm2[threadIdx.x];
        #pragma unroll
        for (int o = 4; o; o >>= 1) v = fmaxf(v, __shfl_xor_sync(0xffu, v, o));
        if (lane == 0) sm2[0] = v;
    }
    __syncthreads();
    return sm2[0];
}

// ---------------- generic batched fp32 GEMM: C = A @ B (TRB=0) or A @ B^T (TRB=1) ----------------
// Tile 64x64, BK=16, 256 threads, 4x4 per thread. Requires M%64==0, N%64==0, K%16==0,
// all leading dims / base offsets multiples of 4 floats (16B).
template<int TRB>
__global__ void __launch_bounds__(256) gemm_f32(
    const float* __restrict__ Ag, const float* __restrict__ Bg, float* __restrict__ Cg,
    int M, int N, int K, int lda, int ldb, int ldc,
    int nInner, long long aOut, long long aIn, long long bOut, long long bIn,
    long long cOut, long long cIn)
{
    const int z  = blockIdx.z;
    const int zo = z / nInner, zi = z - zo * nInner;
    const float* A = Ag + zo * aOut + zi * aIn;
    const float* B = Bg + zo * bOut + zi * bIn;
    float*       C = Cg + zo * cOut + zi * cIn;

    __shared__ float As[16][64];
    __shared__ float Bs[16][64];

    const int tid = threadIdx.x;
    const int tx = tid & 15, ty = tid >> 4;
    const int m0 = blockIdx.y << 6;
    const int n0 = blockIdx.x << 6;

    const int lm  = tid & 63;          // 0..63
    const int lk4 = (tid >> 6) << 2;   // 0,4,8,12

    float acc[4][4];
    #pragma unroll
    for (int i = 0; i < 4; i++)
        #pragma unroll
        for (int j = 0; j < 4; j++) acc[i][j] = 0.f;

    const float* Aptr = A + (long long)(m0 + lm) * lda + lk4;
    const float* Bptr = TRB ? (B + (long long)(n0 + lm) * ldb + lk4)
                            : (B + (long long)(tid >> 4) * ldb + n0 + (tx << 2));

    for (int kt = 0; kt < K; kt += 16) {
        float4 av = *reinterpret_cast<const float4*>(Aptr + kt);
        As[lk4 + 0][lm] = av.x; As[lk4 + 1][lm] = av.y;
        As[lk4 + 2][lm] = av.z; As[lk4 + 3][lm] = av.w;
        if (TRB) {
            float4 bv = *reinterpret_cast<const float4*>(Bptr + kt);
            Bs[lk4 + 0][lm] = bv.x; Bs[lk4 + 1][lm] = bv.y;
            Bs[lk4 + 2][lm] = bv.z; Bs[lk4 + 3][lm] = bv.w;
        } else {
            float4 bv = *reinterpret_cast<const float4*>(Bptr + (long long)kt * ldb);
            *reinterpret_cast<float4*>(&Bs[tid >> 4][tx << 2]) = bv;
        }
        __syncthreads();
        #pragma unroll
        for (int kk = 0; kk < 16; kk++) {
            float4 a = *reinterpret_cast<const float4*>(&As[kk][ty << 2]);
            float4 b = *reinterpret_cast<const float4*>(&Bs[kk][tx << 2]);
            float ar[4] = {a.x, a.y, a.z, a.w};
            float br[4] = {b.x, b.y, b.z, b.w};
            #pragma unroll
            for (int i = 0; i < 4; i++)
                #pragma unroll
                for (int j = 0; j < 4; j++) acc[i][j] += ar[i] * br[j];
        }
        __syncthreads();
    }
    #pragma unroll
    for (int i = 0; i < 4; i++) {
        float4 cv = make_float4(acc[i][0], acc[i][1], acc[i][2], acc[i][3]);
        *reinterpret_cast<float4*>(&C[(long long)(m0 + (ty << 2) + i) * ldc + n0 + (tx << 2)]) = cv;
    }
}

// ---------------- rmsnorm of q_a (rows of 1536), in place ----------------
__global__ void __launch_bounds__(256) rms_q_kernel(float* __restrict__ qa,
                                                    const float* __restrict__ w)
{
    const int row = blockIdx.x;
    float* p = qa + (long long)row * QLORA;
    float v[6]; float ss = 0.f;
    #pragma unroll
    for (int i = 0; i < 6; i++) { v[i] = p[threadIdx.x + i * 256]; ss += v[i] * v[i]; }
    ss = blockSum(ss);
    const float r = rsqrtf(ss / (float)QLORA + 1e-6f);
    #pragma unroll
    for (int i = 0; i < 6; i++) {
        int idx = threadIdx.x + i * 256;
        p[idx] = v[i] * r * w[idx];
    }
}

// ---------------- kv: rms over first 512, rope last 64, in place on Kc rows of 576 ----------------
__global__ void __launch_bounds__(256) rms_rope_kv_kernel(float* __restrict__ Kc,
                                                          const float* __restrict__ w,
                                                          const float* __restrict__ freqs)
{
    const int row = blockIdx.x;            // 0..MTOT-1
    const int t   = row & (SS - 1);        // position within sequence
    float* p = Kc + (long long)row * CDIM;
    float v[2]; float ss = 0.f;
    #pragma unroll
    for (int i = 0; i < 2; i++) { v[i] = p[threadIdx.x + i * 256]; ss += v[i] * v[i]; }
    ss = blockSum(ss);
    const float r = rsqrtf(ss / (float)KVLORA + 1e-6f);
    #pragma unroll
    for (int i = 0; i < 2; i++) {
        int idx = threadIdx.x + i * 256;
        p[idx] = v[i] * r * w[idx];
    }
    if (threadIdx.x < 32) {
        int j = threadIdx.x;
        float c = freqs[t * 64 + 2 * j], s = freqs[t * 64 + 2 * j + 1];
        float e = p[KVLORA + 2 * j], o = p[KVLORA + 2 * j + 1];
        p[KVLORA + 2 * j]     = e * c - o * s;
        p[KVLORA + 2 * j + 1] = e * s + o * c;
    }
}

// ---------------- rope q_pe: read from g_q, write roped into Qc[..., 512:576] ----------------
__global__ void __launch_bounds__(256) rope_q_kernel(const float* __restrict__ q,
                                                     float* __restrict__ Qc,
                                                     const float* __restrict__ freqs)
{
    long long idx = (long long)blockIdx.x * 256 + threadIdx.x;   // MTOT*HH*32 pairs
    if (idx >= (long long)MTOT * HH * 32) return;
    int j = idx & 31;
    int h = (idx >> 5) & (HH - 1);
    int m = (int)(idx >> 10);
    int t = m & (SS - 1);
    float c = freqs[t * 64 + 2 * j], s = freqs[t * 64 + 2 * j + 1];
    const float* qp = q + (long long)m * (HH * QK_HEAD) + h * QK_HEAD + NOPE;
    float e = qp[2 * j], o = qp[2 * j + 1];
    float* d = Qc + (long long)m * (HH * CDIM) + h * CDIM + KVLORA;
    d[2 * j]     = e * c - o * s;
    d[2 * j + 1] = e * s + o * c;
}

// ---------------- softmax over scores rows (len 1024), with scale + causal mask, in place ----------------
__global__ void __launch_bounds__(256) softmax_kernel(float* __restrict__ sc,
                                                      const float* __restrict__ mask)
{
    const long long row = blockIdx.x;           // b*H*S + h*S + s
    const int s = (int)(row & (SS - 1));
    float* p = sc + row * SS;
    const float* mrow = mask + (long long)s * SS;
    float v[4];
    float mx = -INFINITY;
    #pragma unroll
    for (int i = 0; i < 4; i++) {
        int t = threadIdx.x + i * 256;
        v[i] = p[t] * SCALE_F + mrow[t];
        mx = fmaxf(mx, v[i]);
    }
    mx = blockMax(mx);
    float sum = 0.f;
    #pragma unroll
    for (int i = 0; i < 4; i++) { v[i] = __expf(v[i] - mx); sum += v[i]; }
    sum = blockSum(sum);
    const float inv = 1.f / sum;
    #pragma unroll
    for (int i = 0; i < 4; i++) p[threadIdx.x + i * 256] = v[i] * inv;
}

// ---------------- launch ----------------
extern "C" void kernel_launch(void* const* d_in, const int* in_sizes, int n_in,
                              void* d_out, int out_size)
{
    const float* x      = (const float*)d_in[0];
    const float* freqs  = (const float*)d_in[1];
    const float* mask   = (const float*)d_in[2];
    const float* wq_a   = (const float*)d_in[3];
    const float* qnw    = (const float*)d_in[4];
    const float* wq_b   = (const float*)d_in[5];
    const float* wkv_a  = (const float*)d_in[6];
    const float* kvnw   = (const float*)d_in[7];
    const float* wkv_b  = (const float*)d_in[8];
    const float* wo     = (const float*)d_in[9];
    float* out = (float*)d_out;

    float *qa, *q, *Qc, *Kc, *sc, *o1, *o2;
    cudaGetSymbolAddress((void**)&qa, g_qa);
    cudaGetSymbolAddress((void**)&q,  g_q);
    cudaGetSymbolAddress((void**)&Qc, g_Qc);
    cudaGetSymbolAddress((void**)&Kc, g_Kc);
    cudaGetSymbolAddress((void**)&sc, g_sc);
    cudaGetSymbolAddress((void**)&o1, g_o1);
    cudaGetSymbolAddress((void**)&o2, g_o2);

    // 1. qa = x @ wq_a                (2048 x 1536 x 4096)
    gemm_f32<0><<<dim3(QLORA/64, MTOT/64, 1), 256>>>(
        x, wq_a, qa, MTOT, QLORA, DIM, DIM, QLORA, QLORA,
        1, 0, 0, 0, 0, 0, 0);

    // 2. Kc(raw kv) = x @ wkv_a      (2048 x 576 x 4096)
    gemm_f32<0><<<dim3(CDIM/64, MTOT/64, 1), 256>>>(
        x, wkv_a, Kc, MTOT, CDIM, DIM, DIM, CDIM, CDIM,
        1, 0, 0, 0, 0, 0, 0);

    // 3. rmsnorm qa (in place)
    rms_q_kernel<<<MTOT, 256>>>(qa, qnw);

    // 4. kv rms (first 512) + rope k_pe (in place on Kc)
    rms_rope_kv_kernel<<<MTOT, 256>>>(Kc, kvnw, freqs);

    // 5. q = qa @ wq_b               (2048 x 6144 x 1536)
    gemm_f32<0><<<dim3(HH*QK_HEAD/64, MTOT/64, 1), 256>>>(
        qa, wq_b, q, MTOT, HH*QK_HEAD, QLORA, QLORA, HH*QK_HEAD, HH*QK_HEAD,
        1, 0, 0, 0, 0, 0, 0);

    // 6. rope q_pe -> Qc[...,512:576]
    rope_q_kernel<<<(MTOT*HH*32)/256, 256>>>(q, Qc, freqs);

    // 7. q_abs: per head, q_nope @ wkv_b[h,:128,:] -> Qc[...,0:512]
    //    (2048 x 512 x 128), z = h  (nInner=1 so zo=h)
    gemm_f32<0><<<dim3(KVLORA/64, MTOT/64, HH), 256>>>(
        q, wkv_b, Qc, MTOT, KVLORA, NOPE,
        HH*QK_HEAD, KVLORA, HH*CDIM,
        1, QK_HEAD, 0, (long long)(NOPE+VD)*KVLORA, 0, CDIM, 0);

    // 8. scores: per (b,h), Qc_bh @ Kc_b^T   (1024 x 1024 x 576), z = b*H + h
    gemm_f32<1><<<dim3(SS/64, SS/64, BB*HH), 256>>>(
        Qc, Kc, sc, SS, SS, CDIM,
        HH*CDIM, CDIM, SS,
        HH,
        (long long)SS*HH*CDIM, CDIM,          // A: per-b, per-h
        (long long)SS*CDIM,    0,             // B: per-b
        (long long)HH*SS*SS,   (long long)SS*SS);  // C: per-b, per-h

    // 9. softmax with scale + mask
    softmax_kernel<<<BB*HH*SS, 256>>>(sc, mask);

    // 10. o1 = probs @ kv_n          (1024 x 512 x 1024), z = b*H + h
    gemm_f32<0><<<dim3(KVLORA/64, SS/64, BB*HH), 256>>>(
        sc, Kc, o1, SS, KVLORA, SS,
        SS, CDIM, HH*KVLORA,
        HH,
        (long long)HH*SS*SS,   (long long)SS*SS,
        (long long)SS*CDIM,    0,
        (long long)SS*HH*KVLORA, KVLORA);

    // 11. o2 = o1 @ wkv_b[h,128:,:]^T  (2048 x 128 x 512), z = h
    //     FIX (unbenched, R1): base pointer pre-offset by NOPE*KVLORA,
    //     per-head stride (NOPE+VD)*KVLORA passed as bOut.
    gemm_f32<1><<<dim3(VD/64, MTOT/64, HH), 256>>>(
        o1, wkv_b + (long long)NOPE*KVLORA, o2, MTOT, VD, KVLORA,
        HH*KVLORA, KVLORA, DIM,
        1, KVLORA, 0,
        (long long)(NOPE+VD)*KVLORA, 0,
        VD, 0);

    // 12. out = o2 @ wo              (2048 x 4096 x 4096)
    gemm_f32<0><<<dim3(DIM/64, MTOT/64, 1), 256>>>(
        o2, wo, out, MTOT, DIM, DIM, DIM, DIM, DIM,
        1, 0, 0, 0, 0, 0, 0);
}

// round 5
// speedup vs baseline: 2.4477x; 2.4477x over previous
#include <cuda_runtime.h>
#include <cuda_bf16.h>
#include <math.h>
#include <stdint.h>

typedef __nv_bfloat16 bf16;

// ---------------- problem constants ----------------
#define BB 2
#define SS 1024
#define DIM 4096
#define HH 32
#define QLORA 1536
#define KVLORA 512
#define NOPE 128
#define ROPE 64
#define VD 128
#define QK_HEAD 192
#define MTOT (BB*SS)
#define CDIM 576
#define SCALE_F 0.07216878364870323f

// ---------------- fp32 scratch ----------------
__device__ __align__(16) float g_qa[MTOT * QLORA];
__device__ __align__(16) float g_Kc[MTOT * CDIM];
__device__ __align__(16) float g_sc[BB*HH*SS*SS];          // 67.1M

// ---------------- split bf16 scratch (hi / lo pairs) ----------------
__device__ __align__(16) bf16 g_xh[MTOT*DIM],            g_xl[MTOT*DIM];
__device__ __align__(16) bf16 g_wqaTh[QLORA*DIM],        g_wqaTl[QLORA*DIM];
__device__ __align__(16) bf16 g_wkvaTh[CDIM*DIM],        g_wkvaTl[CDIM*DIM];
__device__ __align__(16) bf16 g_qah[MTOT*QLORA],         g_qal[MTOT*QLORA];
__device__ __align__(16) bf16 g_wqbTh[HH*QK_HEAD*QLORA], g_wqbTl[HH*QK_HEAD*QLORA];
__device__ __align__(16) bf16 g_qh[MTOT*HH*QK_HEAD],     g_ql[MTOT*HH*QK_HEAD];
__device__ __align__(16) bf16 g_wb1h[HH*KVLORA*NOPE],    g_wb1l[HH*KVLORA*NOPE];
__device__ __align__(16) bf16 g_Qch[MTOT*HH*CDIM],       g_Qcl[MTOT*HH*CDIM];
__device__ __align__(16) bf16 g_Kch[MTOT*CDIM],          g_Kcl[MTOT*CDIM];
__device__ __align__(16) bf16 g_KcTh[BB*KVLORA*SS],      g_KcTl[BB*KVLORA*SS];
__device__ __align__(16) bf16 g_prh[BB*HH*SS*SS],        g_prl[BB*HH*SS*SS];
__device__ __align__(16) bf16 g_o1h[MTOT*HH*KVLORA],     g_o1l[MTOT*HH*KVLORA];
__device__ __align__(16) bf16 g_wkvbh[HH*(NOPE+VD)*KVLORA], g_wkvbl[HH*(NOPE+VD)*KVLORA];
__device__ __align__(16) bf16 g_o2h[MTOT*DIM],           g_o2l[MTOT*DIM];
__device__ __align__(16) bf16 g_woTh[DIM*DIM],           g_woTl[DIM*DIM];

__device__ __forceinline__ void split2(float v, bf16& h, bf16& l) {
    h = __float2bfloat16(v);
    l = __float2bfloat16(v - __bfloat162float(h));
}
__device__ __forceinline__ float joinv(bf16 h, bf16 l) {
    return __bfloat162float(h) + __bfloat162float(l);
}

// ---------------- reductions ----------------
__device__ __forceinline__ float blockSum(float v) {
    __shared__ float sm[8];
    __syncthreads();
    int lane = threadIdx.x & 31, w = threadIdx.x >> 5;
    #pragma unroll
    for (int o = 16; o; o >>= 1) v += __shfl_xor_sync(0xffffffffu, v, o);
    if (lane == 0) sm[w] = v;
    __syncthreads();
    if (threadIdx.x < 8) {
        v = sm[threadIdx.x];
        #pragma unroll
        for (int o = 4; o; o >>= 1) v += __shfl_xor_sync(0xffu, v, o);
        if (lane == 0) sm[0] = v;
    }
    __syncthreads();
    return sm[0];
}
__device__ __forceinline__ float blockMax(float v) {
    __shared__ float sm2[8];
    __syncthreads();
    int lane = threadIdx.x & 31, w = threadIdx.x >> 5;
    #pragma unroll
    for (int o = 16; o; o >>= 1) v = fmaxf(v, __shfl_xor_sync(0xffffffffu, v, o));
    if (lane == 0) sm2[w] = v;
    __syncthreads();
    if (threadIdx.x < 8) {
        v = sm2[threadIdx.x];
        #pragma unroll
        for (int o = 4; o; o >>= 1) v = fmaxf(v, __shfl_xor_sync(0xffu, v, o));
        if (lane == 0) sm2[0] = v;
    }
    __syncthreads();
    return sm2[0];
}

// ================= split conversion kernels =================
__global__ void __launch_bounds__(256) splitf(const float* __restrict__ src,
                                              bf16* __restrict__ hi, bf16* __restrict__ lo,
                                              long long n)
{
    long long i = (long long)blockIdx.x * 256 + threadIdx.x;
    if (i >= n) return;
    split2(src[i], hi[i], lo[i]);
}

// transpose + split: src fp32 [R rows][C cols] (ld=lds) -> dst bf16 [C][R] (ld=ldd); batched
__global__ void __launch_bounds__(256) splitTf(const float* __restrict__ src,
                                               bf16* __restrict__ hiT, bf16* __restrict__ loT,
                                               int C, int lds, int ldd,
                                               long long srcB, long long dstB)
{
    __shared__ float t[32][33];
    const float* s = src + (long long)blockIdx.z * srcB;
    bf16* dh = hiT + (long long)blockIdx.z * dstB;
    bf16* dl = loT + (long long)blockIdx.z * dstB;
    int c0 = blockIdx.x * 32, r0 = blockIdx.y * 32;
    int tx = threadIdx.x & 31, ty = threadIdx.x >> 5;
    #pragma unroll
    for (int i = 0; i < 32; i += 8)
        t[ty + i][tx] = s[(long long)(r0 + ty + i) * lds + c0 + tx];
    __syncthreads();
    #pragma unroll
    for (int i = 0; i < 32; i += 8) {
        float v = t[tx][ty + i];
        bf16 h, l; split2(v, h, l);
        long long o = (long long)(c0 + ty + i) * ldd + r0 + tx;
        dh[o] = h; dl[o] = l;
    }
}

// ================= bf16-split tensor-core GEMM =================
// C[M,N] = sum_k A[m,k]*B[n,k]   (both K-major, hi+lo split operands)
// CTA 128x64, BK=32, 256 thr, 8 warps (4M x 2N), warp 32x32.
// OUTS==0: write fp32 C.  OUTS==1: write split bf16 (Chi, Clo).
#define SPAD 40
template<int OUTS>
__global__ void __launch_bounds__(256) gemm_bf16s(
    const bf16* __restrict__ Ahi, const bf16* __restrict__ Alo,
    const bf16* __restrict__ Bhi, const bf16* __restrict__ Blo,
    float* __restrict__ Cf, bf16* __restrict__ Chi, bf16* __restrict__ Clo,
    int M, int N, int K, int lda, int ldb, int ldc,
    int nInner, long long aOut, long long aIn, long long bOut, long long bIn,
    long long cOut, long long cIn)
{
    const int z = blockIdx.z;
    const int zo = z / nInner, zi = z - zo * nInner;
    const long long aoff = zo * aOut + zi * aIn;
    const long long boff = zo * bOut + zi * bIn;
    const long long coff = zo * cOut + zi * cIn;

    __shared__ bf16 As[2][128 * SPAD];
    __shared__ bf16 Bs[2][64 * SPAD];

    const int tid = threadIdx.x;
    const int m0 = blockIdx.y << 7;
    const int n0 = blockIdx.x << 6;
    const int wid = tid >> 5, lane = tid & 31;
    const int wm = (wid & 3) * 32;
    const int wn = (wid >> 2) * 32;

    float acc[2][4][4];
    #pragma unroll
    for (int a = 0; a < 2; a++)
        #pragma unroll
        for (int b = 0; b < 4; b++)
            #pragma unroll
            for (int c = 0; c < 4; c++) acc[a][b][c] = 0.f;

    // ldmatrix lane geometry
    const int g = lane >> 3, lr = lane & 7;
    const int a_row = (g & 1) * 8 + lr, a_kc = (g >> 1) * 8;
    const int b_row = (g >> 1) * 8 + lr, b_kc = (g & 1) * 8;

    const uint32_t sA0 = (uint32_t)__cvta_generic_to_shared(&As[0][0]);
    const uint32_t sA1 = (uint32_t)__cvta_generic_to_shared(&As[1][0]);
    const uint32_t sB0 = (uint32_t)__cvta_generic_to_shared(&Bs[0][0]);
    const uint32_t sB1 = (uint32_t)__cvta_generic_to_shared(&Bs[1][0]);

    // global load geometry: 4-half chunks
    const int ar = tid >> 3;            // base row (A uses ar, ar+32, ar+64, ar+96)
    const int ac = (tid & 7) * 4;       // col within BK

    for (int kt = 0; kt < K; kt += 32) {
        #pragma unroll
        for (int i = 0; i < 4; i++) {
            int r = ar + i * 32;
            long long go = aoff + (long long)(m0 + r) * lda + kt + ac;
            *(uint2*)&As[0][r * SPAD + ac] = *(const uint2*)(Ahi + go);
            *(uint2*)&As[1][r * SPAD + ac] = *(const uint2*)(Alo + go);
        }
        #pragma unroll
        for (int i = 0; i < 2; i++) {
            int r = ar + i * 32;
            long long go = boff + (long long)(n0 + r) * ldb + kt + ac;
            *(uint2*)&Bs[0][r * SPAD + ac] = *(const uint2*)(Bhi + go);
            *(uint2*)&Bs[1][r * SPAD + ac] = *(const uint2*)(Blo + go);
        }
        __syncthreads();

        #pragma unroll
        for (int kk = 0; kk < 2; kk++) {
            uint32_t afr[2][2][4];   // [mi][hi/lo][4]
            #pragma unroll
            for (int mi = 0; mi < 2; mi++) {
                uint32_t off = (uint32_t)((wm + mi * 16 + a_row) * SPAD + kk * 16 + a_kc) * 2;
                asm volatile("ldmatrix.sync.aligned.m8n8.x4.shared.b16 {%0,%1,%2,%3},[%4];"
                    : "=r"(afr[mi][0][0]), "=r"(afr[mi][0][1]), "=r"(afr[mi][0][2]), "=r"(afr[mi][0][3])
                    : "r"(sA0 + off));
                asm volatile("ldmatrix.sync.aligned.m8n8.x4.shared.b16 {%0,%1,%2,%3},[%4];"
                    : "=r"(afr[mi][1][0]), "=r"(afr[mi][1][1]), "=r"(afr[mi][1][2]), "=r"(afr[mi][1][3])
                    : "r"(sA1 + off));
            }
            uint32_t bfr[2][4][2];   // [hi/lo][ni][2]
            #pragma unroll
            for (int j = 0; j < 2; j++) {     // n-range 16*j
                uint32_t off = (uint32_t)((wn + j * 16 + b_row) * SPAD + kk * 16 + b_kc) * 2;
                uint32_t r0, r1, r2, r3;
                asm volatile("ldmatrix.sync.aligned.m8n8.x4.shared.b16 {%0,%1,%2,%3},[%4];"
                    : "=r"(r0), "=r"(r1), "=r"(r2), "=r"(r3) : "r"(sB0 + off));
                bfr[0][j*2][0] = r0; bfr[0][j*2][1] = r1;
                bfr[0][j*2+1][0] = r2; bfr[0][j*2+1][1] = r3;
                asm volatile("ldmatrix.sync.aligned.m8n8.x4.shared.b16 {%0,%1,%2,%3},[%4];"
                    : "=r"(r0), "=r"(r1), "=r"(r2), "=r"(r3) : "r"(sB1 + off));
                bfr[1][j*2][0] = r0; bfr[1][j*2][1] = r1;
                bfr[1][j*2+1][0] = r2; bfr[1][j*2+1][1] = r3;
            }
            #pragma unroll
            for (int mi = 0; mi < 2; mi++)
                #pragma unroll
                for (int ni = 0; ni < 4; ni++) {
                    float* c = acc[mi][ni];
                    #define MMA_ONE(A_, B_) \
                        asm volatile("mma.sync.aligned.m16n8k16.row.col.f32.bf16.bf16.f32 " \
                            "{%0,%1,%2,%3},{%4,%5,%6,%7},{%8,%9},{%0,%1,%2,%3};" \
                            : "+f"(c[0]), "+f"(c[1]), "+f"(c[2]), "+f"(c[3]) \
                            : "r"((A_)[0]), "r"((A_)[1]), "r"((A_)[2]), "r"((A_)[3]), \
                              "r"((B_)[0]), "r"((B_)[1]))
                    MMA_ONE(afr[mi][0], bfr[0][ni]);   // hi*hi
                    MMA_ONE(afr[mi][0], bfr[1][ni]);   // hi*lo
                    MMA_ONE(afr[mi][1], bfr[0][ni]);   // lo*hi
                    #undef MMA_ONE
                }
        }
        __syncthreads();
    }

    // epilogue
    const int er = lane >> 2, ec = (lane & 3) * 2;
    #pragma unroll
    for (int mi = 0; mi < 2; mi++)
        #pragma unroll
        for (int ni = 0; ni < 4; ni++) {
            long long base = coff + (long long)(m0 + wm + mi * 16 + er) * ldc + n0 + wn + ni * 8 + ec;
            long long base2 = base + (long long)8 * ldc;
            float v0 = acc[mi][ni][0], v1 = acc[mi][ni][1];
            float v2 = acc[mi][ni][2], v3 = acc[mi][ni][3];
            if (OUTS == 0) {
                Cf[base] = v0; Cf[base + 1] = v1;
                Cf[base2] = v2; Cf[base2 + 1] = v3;
            } else {
                bf16 h, l;
                split2(v0, h, l); Chi[base] = h;      Clo[base] = l;
                split2(v1, h, l); Chi[base + 1] = h;  Clo[base + 1] = l;
                split2(v2, h, l); Chi[base2] = h;     Clo[base2] = l;
                split2(v3, h, l); Chi[base2 + 1] = h; Clo[base2 + 1] = l;
            }
        }
}

// ================= fused elementwise kernels =================
// rmsnorm qa rows (1536) -> split bf16
__global__ void __launch_bounds__(256) rms_q_kernel(const float* __restrict__ qa,
                                                    const float* __restrict__ w,
                                                    bf16* __restrict__ oh, bf16* __restrict__ ol)
{
    const int row = blockIdx.x;
    const float* p = qa + (long long)row * QLORA;
    float v[6]; float ss = 0.f;
    #pragma unroll
    for (int i = 0; i < 6; i++) { v[i] = p[threadIdx.x + i * 256]; ss += v[i] * v[i]; }
    ss = blockSum(ss);
    const float r = rsqrtf(ss / (float)QLORA + 1e-6f);
    #pragma unroll
    for (int i = 0; i < 6; i++) {
        int idx = threadIdx.x + i * 256;
        bf16 h, l; split2(v[i] * r * w[idx], h, l);
        long long o = (long long)row * QLORA + idx;
        oh[o] = h; ol[o] = l;
    }
}

// kv: rms first 512 + rope last 64; writes fp32 (for KcT transpose source) AND split bf16
__global__ void __launch_bounds__(256) rms_rope_kv_kernel(float* __restrict__ Kc,
                                                          const float* __restrict__ w,
                                                          const float* __restrict__ freqs,
                                                          bf16* __restrict__ oh, bf16* __restrict__ ol)
{
    const int row = blockIdx.x;
    const int t = row & (SS - 1);
    float* p = Kc + (long long)row * CDIM;
    float v[2]; float ss = 0.f;
    #pragma unroll
    for (int i = 0; i < 2; i++) { v[i] = p[threadIdx.x + i * 256]; ss += v[i] * v[i]; }
    ss = blockSum(ss);
    const float r = rsqrtf(ss / (float)KVLORA + 1e-6f);
    #pragma unroll
    for (int i = 0; i < 2; i++) {
        int idx = threadIdx.x + i * 256;
        float nv = v[i] * r * w[idx];
        p[idx] = nv;
        bf16 h, l; split2(nv, h, l);
        long long o = (long long)row * CDIM + idx;
        oh[o] = h; ol[o] = l;
    }
    if (threadIdx.x < 32) {
        int j = threadIdx.x;
        float c = freqs[t * 64 + 2 * j], s = freqs[t * 64 + 2 * j + 1];
        float e = p[KVLORA + 2 * j], o = p[KVLORA + 2 * j + 1];
        float oe = e * c - o * s, oo = e * s + o * c;
        p[KVLORA + 2 * j] = oe; p[KVLORA + 2 * j + 1] = oo;
        bf16 h, l;
        long long b = (long long)row * CDIM + KVLORA + 2 * j;
        split2(oe, h, l); oh[b] = h;     ol[b] = l;
        split2(oo, h, l); oh[b + 1] = h; ol[b + 1] = l;
    }
}

// rope q_pe: read split q, write split into Qc[..., 512:576]
__global__ void __launch_bounds__(256) rope_q_kernel(const bf16* __restrict__ qh,
                                                     const bf16* __restrict__ ql,
                                                     bf16* __restrict__ Qh, bf16* __restrict__ Ql,
                                                     const float* __restrict__ freqs)
{
    long long idx = (long long)blockIdx.x * 256 + threadIdx.x;
    if (idx >= (long long)MTOT * HH * 32) return;
    int j = idx & 31;
    int h = (idx >> 5) & (HH - 1);
    int m = (int)(idx >> 10);
    int t = m & (SS - 1);
    float c = freqs[t * 64 + 2 * j], s = freqs[t * 64 + 2 * j + 1];
    long long qb = (long long)m * (HH * QK_HEAD) + h * QK_HEAD + NOPE + 2 * j;
    float e = joinv(qh[qb], ql[qb]);
    float o = joinv(qh[qb + 1], ql[qb + 1]);
    long long d = (long long)m * (HH * CDIM) + h * CDIM + KVLORA + 2 * j;
    bf16 hh, ll;
    split2(e * c - o * s, hh, ll); Qh[d] = hh;     Ql[d] = ll;
    split2(e * s + o * c, hh, ll); Qh[d + 1] = hh; Ql[d + 1] = ll;
}

// softmax rows (1024) with scale + mask; read fp32 scores, write split bf16 probs
__global__ void __launch_bounds__(256) softmax_kernel(const float* __restrict__ sc,
                                                      const float* __restrict__ mask,
                                                      bf16* __restrict__ ph, bf16* __restrict__ pl)
{
    const long long row = blockIdx.x;
    const int s = (int)(row & (SS - 1));
    const float* p = sc + row * SS;
    const float* mrow = mask + (long long)s * SS;
    float v[4];
    float mx = -INFINITY;
    #pragma unroll
    for (int i = 0; i < 4; i++) {
        int t = threadIdx.x + i * 256;
        v[i] = p[t] * SCALE_F + mrow[t];
        mx = fmaxf(mx, v[i]);
    }
    mx = blockMax(mx);
    float sum = 0.f;
    #pragma unroll
    for (int i = 0; i < 4; i++) { v[i] = __expf(v[i] - mx); sum += v[i]; }
    sum = blockSum(sum);
    const float inv = 1.f / sum;
    #pragma unroll
    for (int i = 0; i < 4; i++) {
        int t = threadIdx.x + i * 256;
        bf16 h, l; split2(v[i] * inv, h, l);
        ph[row * SS + t] = h; pl[row * SS + t] = l;
    }
}

// ---------------- launch ----------------
extern "C" void kernel_launch(void* const* d_in, const int* in_sizes, int n_in,
                              void* d_out, int out_size)
{
    const float* x     = (const float*)d_in[0];
    const float* freqs = (const float*)d_in[1];
    const float* mask  = (const float*)d_in[2];
    const float* wq_a  = (const float*)d_in[3];
    const float* qnw   = (const float*)d_in[4];
    const float* wq_b  = (const float*)d_in[5];
    const float* wkv_a = (const float*)d_in[6];
    const float* kvnw  = (const float*)d_in[7];
    const float* wkv_b = (const float*)d_in[8];
    const float* wo    = (const float*)d_in[9];
    float* out = (float*)d_out;

    float *qa, *Kc, *sc;
    cudaGetSymbolAddress((void**)&qa, g_qa);
    cudaGetSymbolAddress((void**)&Kc, g_Kc);
    cudaGetSymbolAddress((void**)&sc, g_sc);

    bf16 *xh,*xl,*wqaTh,*wqaTl,*wkvaTh,*wkvaTl,*qah,*qal,*wqbTh,*wqbTl,*qh,*ql;
    bf16 *wb1h,*wb1l,*Qch,*Qcl,*Kch,*Kcl,*KcTh,*KcTl,*prh,*prl,*o1h,*o1l;
    bf16 *wkvbh,*wkvbl,*o2h,*o2l,*woTh,*woTl;
    cudaGetSymbolAddress((void**)&xh, g_xh);       cudaGetSymbolAddress((void**)&xl, g_xl);
    cudaGetSymbolAddress((void**)&wqaTh, g_wqaTh); cudaGetSymbolAddress((void**)&wqaTl, g_wqaTl);
    cudaGetSymbolAddress((void**)&wkvaTh, g_wkvaTh); cudaGetSymbolAddress((void**)&wkvaTl, g_wkvaTl);
    cudaGetSymbolAddress((void**)&qah, g_qah);     cudaGetSymbolAddress((void**)&qal, g_qal);
    cudaGetSymbolAddress((void**)&wqbTh, g_wqbTh); cudaGetSymbolAddress((void**)&wqbTl, g_wqbTl);
    cudaGetSymbolAddress((void**)&qh, g_qh);       cudaGetSymbolAddress((void**)&ql, g_ql);
    cudaGetSymbolAddress((void**)&wb1h, g_wb1h);   cudaGetSymbolAddress((void**)&wb1l, g_wb1l);
    cudaGetSymbolAddress((void**)&Qch, g_Qch);     cudaGetSymbolAddress((void**)&Qcl, g_Qcl);
    cudaGetSymbolAddress((void**)&Kch, g_Kch);     cudaGetSymbolAddress((void**)&Kcl, g_Kcl);
    cudaGetSymbolAddress((void**)&KcTh, g_KcTh);   cudaGetSymbolAddress((void**)&KcTl, g_KcTl);
    cudaGetSymbolAddress((void**)&prh, g_prh);     cudaGetSymbolAddress((void**)&prl, g_prl);
    cudaGetSymbolAddress((void**)&o1h, g_o1h);     cudaGetSymbolAddress((void**)&o1l, g_o1l);
    cudaGetSymbolAddress((void**)&wkvbh, g_wkvbh); cudaGetSymbolAddress((void**)&wkvbl, g_wkvbl);
    cudaGetSymbolAddress((void**)&o2h, g_o2h);     cudaGetSymbolAddress((void**)&o2l, g_o2l);
    cudaGetSymbolAddress((void**)&woTh, g_woTh);   cudaGetSymbolAddress((void**)&woTl, g_woTl);

    // ---- operand preparation: split + (transposed) split ----
    splitf<<<(MTOT*(long long)DIM + 255)/256, 256>>>(x, xh, xl, (long long)MTOT*DIM);
    splitf<<<(HH*(NOPE+VD)*(long long)KVLORA + 255)/256, 256>>>(wkv_b, wkvbh, wkvbl,
                                                                (long long)HH*(NOPE+VD)*KVLORA);
    splitTf<<<dim3(QLORA/32, DIM/32, 1), 256>>>(wq_a, wqaTh, wqaTl, QLORA, QLORA, DIM, 0, 0);
    splitTf<<<dim3(CDIM/32, DIM/32, 1), 256>>>(wkv_a, wkvaTh, wkvaTl, CDIM, CDIM, DIM, 0, 0);
    splitTf<<<dim3(HH*QK_HEAD/32, QLORA/32, 1), 256>>>(wq_b, wqbTh, wqbTl,
                                                       HH*QK_HEAD, HH*QK_HEAD, QLORA, 0, 0);
    splitTf<<<dim3(DIM/32, DIM/32, 1), 256>>>(wo, woTh, woTl, DIM, DIM, DIM, 0, 0);
    // wkv_b[h, 0:128, 0:512] -> [h][512][128]
    splitTf<<<dim3(KVLORA/32, NOPE/32, HH), 256>>>(wkv_b, wb1h, wb1l,
        KVLORA, KVLORA, NOPE, (long long)(NOPE+VD)*KVLORA, (long long)KVLORA*NOPE);

    // 1. qa = x @ wq_a  (fp32 out, rms needs exact rows)
    gemm_bf16s<0><<<dim3(QLORA/64, MTOT/128, 1), 256>>>(
        xh, xl, wqaTh, wqaTl, qa, nullptr, nullptr,
        MTOT, QLORA, DIM, DIM, DIM, QLORA, 1, 0, 0, 0, 0, 0, 0);

    // 2. Kc_raw = x @ wkv_a  (fp32 out)
    gemm_bf16s<0><<<dim3(CDIM/64, MTOT/128, 1), 256>>>(
        xh, xl, wkvaTh, wkvaTl, Kc, nullptr, nullptr,
        MTOT, CDIM, DIM, DIM, DIM, CDIM, 1, 0, 0, 0, 0, 0, 0);

    // 3. rmsnorm qa -> split
    rms_q_kernel<<<MTOT, 256>>>(qa, qnw, qah, qal);

    // 4. kv rms + rope k_pe -> fp32 Kc (in place) + split Kc_b
    rms_rope_kv_kernel<<<MTOT, 256>>>(Kc, kvnw, freqs, Kch, Kcl);

    // 4b. KcT (per batch): Kc[t][0:512] -> [512][1024]
    splitTf<<<dim3(KVLORA/32, SS/32, BB), 256>>>(Kc, KcTh, KcTl,
        KVLORA, CDIM, SS, (long long)SS*CDIM, (long long)KVLORA*SS);

    // 5. q = qa_n @ wq_b  (split out)
    gemm_bf16s<1><<<dim3(HH*QK_HEAD/64, MTOT/128, 1), 256>>>(
        qah, qal, wqbTh, wqbTl, nullptr, qh, ql,
        MTOT, HH*QK_HEAD, QLORA, QLORA, QLORA, HH*QK_HEAD, 1, 0, 0, 0, 0, 0, 0);

    // 6. rope q_pe -> Qc[...,512:576] (split)
    rope_q_kernel<<<(MTOT*HH*32)/256, 256>>>(qh, ql, Qch, Qcl, freqs);

    // 7. q_abs per head: q_nope @ wkv_b[h,:128,:]^T' -> Qc[...,0:512] (split), z=h
    gemm_bf16s<1><<<dim3(KVLORA/64, MTOT/128, HH), 256>>>(
        qh, ql, wb1h, wb1l, nullptr, Qch, Qcl,
        MTOT, KVLORA, NOPE, HH*QK_HEAD, NOPE, HH*CDIM,
        1, QK_HEAD, 0, (long long)KVLORA*NOPE, 0, CDIM, 0);

    // 8. scores per (b,h): Qc_bh @ Kc_b^T  (fp32 out), z=b*H+h
    gemm_bf16s<0><<<dim3(SS/64, SS/128, BB*HH), 256>>>(
        Qch, Qcl, Kch, Kcl, sc, nullptr, nullptr,
        SS, SS, CDIM, HH*CDIM, CDIM, SS,
        HH,
        (long long)SS*HH*CDIM, CDIM,
        (long long)SS*CDIM, 0,
        (long long)HH*SS*SS, (long long)SS*SS);

    // 9. softmax -> split probs
    softmax_kernel<<<BB*HH*SS, 256>>>(sc, mask, prh, prl);

    // 10. o1 = probs @ kv_n  (B = KcT, split out), z=b*H+h
    gemm_bf16s<1><<<dim3(KVLORA/64, SS/128, BB*HH), 256>>>(
        prh, prl, KcTh, KcTl, nullptr, o1h, o1l,
        SS, KVLORA, SS, SS, SS, HH*KVLORA,
        HH,
        (long long)HH*SS*SS, (long long)SS*SS,
        (long long)KVLORA*SS, 0,
        (long long)SS*HH*KVLORA, (long long)KVLORA);

    // 11. o2 = o1 @ wkv_b[h,128:,:]^T  (split out), z=h
    gemm_bf16s<1><<<dim3(VD/64, MTOT/128, HH), 256>>>(
        o1h, o1l, wkvbh + (long long)NOPE*KVLORA, wkvbl + (long long)NOPE*KVLORA,
        nullptr, o2h, o2l,
        MTOT, VD, KVLORA, HH*KVLORA, KVLORA, DIM,
        1, (long long)KVLORA, 0,
        (long long)(NOPE+VD)*KVLORA, 0,
        (long long)VD, 0);

    // 12. out = o2 @ wo  (fp32 out)
    gemm_bf16s<0><<<dim3(DIM/64, MTOT/128, 1), 256>>>(
        o2h, o2l, woTh, woTl, out, nullptr, nullptr,
        MTOT, DIM, DIM, DIM, DIM, DIM, 1, 0, 0, 0, 0, 0, 0);
}

// round 13
// speedup vs baseline: 2.7951x; 1.1419x over previous
#include <cuda_runtime.h>
#include <cuda_bf16.h>
#include <math.h>
#include <stdint.h>

typedef __nv_bfloat16 bf16;

// ---------------- problem constants ----------------
#define BB 2
#define SS 1024
#define DIM 4096
#define HH 32
#define QLORA 1536
#define KVLORA 512
#define NOPE 128
#define ROPE 64
#define VD 128
#define QK_HEAD 192
#define MTOT (BB*SS)
#define CDIM 576
#define SCALE_F 0.07216878364870323f

// ---------------- fp32 scratch ----------------
__device__ __align__(16) float g_qa[MTOT * QLORA];
__device__ __align__(16) float g_Kc[MTOT * CDIM];
__device__ __align__(16) float g_sc[BB*HH*SS*SS];          // 67.1M

// ---------------- split bf16 scratch (hi / lo pairs) ----------------
__device__ __align__(16) bf16 g_xh[MTOT*DIM],            g_xl[MTOT*DIM];
__device__ __align__(16) bf16 g_wqaTh[QLORA*DIM],        g_wqaTl[QLORA*DIM];
__device__ __align__(16) bf16 g_wkvaTh[CDIM*DIM],        g_wkvaTl[CDIM*DIM];
__device__ __align__(16) bf16 g_qah[MTOT*QLORA],         g_qal[MTOT*QLORA];
__device__ __align__(16) bf16 g_wqbTh[HH*QK_HEAD*QLORA], g_wqbTl[HH*QK_HEAD*QLORA];
__device__ __align__(16) bf16 g_qh[MTOT*HH*QK_HEAD],     g_ql[MTOT*HH*QK_HEAD];
__device__ __align__(16) bf16 g_wb1h[HH*KVLORA*NOPE],    g_wb1l[HH*KVLORA*NOPE];
__device__ __align__(16) bf16 g_Qch[MTOT*HH*CDIM],       g_Qcl[MTOT*HH*CDIM];
__device__ __align__(16) bf16 g_Kch[MTOT*CDIM],          g_Kcl[MTOT*CDIM];
__device__ __align__(16) bf16 g_KcTh[BB*KVLORA*SS],      g_KcTl[BB*KVLORA*SS];
__device__ __align__(16) bf16 g_prh[BB*HH*SS*SS],        g_prl[BB*HH*SS*SS];
__device__ __align__(16) bf16 g_o1h[MTOT*HH*KVLORA],     g_o1l[MTOT*HH*KVLORA];
__device__ __align__(16) bf16 g_wkvbh[HH*(NOPE+VD)*KVLORA], g_wkvbl[HH*(NOPE+VD)*KVLORA];
__device__ __align__(16) bf16 g_o2h[MTOT*DIM],           g_o2l[MTOT*DIM];
__device__ __align__(16) bf16 g_woTh[DIM*DIM],           g_woTl[DIM*DIM];

__device__ __forceinline__ void split2(float v, bf16& h, bf16& l) {
    h = __float2bfloat16(v);
    l = __float2bfloat16(v - __bfloat162float(h));
}
__device__ __forceinline__ float joinv(bf16 h, bf16 l) {
    return __bfloat162float(h) + __bfloat162float(l);
}

// ---------------- reductions ----------------
__device__ __forceinline__ float blockSum(float v) {
    __shared__ float sm[8];
    __syncthreads();
    int lane = threadIdx.x & 31, w = threadIdx.x >> 5;
    #pragma unroll
    for (int o = 16; o; o >>= 1) v += __shfl_xor_sync(0xffffffffu, v, o);
    if (lane == 0) sm[w] = v;
    __syncthreads();
    if (threadIdx.x < 8) {
        v = sm[threadIdx.x];
        #pragma unroll
        for (int o = 4; o; o >>= 1) v += __shfl_xor_sync(0xffu, v, o);
        if (lane == 0) sm[0] = v;
    }
    __syncthreads();
    return sm[0];
}
__device__ __forceinline__ float blockMax(float v) {
    __shared__ float sm2[8];
    __syncthreads();
    int lane = threadIdx.x & 31, w = threadIdx.x >> 5;
    #pragma unroll
    for (int o = 16; o; o >>= 1) v = fmaxf(v, __shfl_xor_sync(0xffffffffu, v, o));
    if (lane == 0) sm2[w] = v;
    __syncthreads();
    if (threadIdx.x < 8) {
        v = sm2[threadIdx.x];
        #pragma unroll
        for (int o = 4; o; o >>= 1) v = fmaxf(v, __shfl_xor_sync(0xffu, v, o));
        if (lane == 0) sm2[0] = v;
    }
    __syncthreads();
    return sm2[0];
}

// ================= split conversion kernels =================
__global__ void __launch_bounds__(256) splitf(const float* __restrict__ src,
                                              bf16* __restrict__ hi, bf16* __restrict__ lo,
                                              long long n)
{
    long long i = (long long)blockIdx.x * 256 + threadIdx.x;
    if (i >= n) return;
    split2(src[i], hi[i], lo[i]);
}

// transpose + split: src fp32 [R rows][C cols] (ld=lds) -> dst bf16 [C][R] (ld=ldd); batched
__global__ void __launch_bounds__(256) splitTf(const float* __restrict__ src,
                                               bf16* __restrict__ hiT, bf16* __restrict__ loT,
                                               int C, int lds, int ldd,
                                               long long srcB, long long dstB)
{
    __shared__ float t[32][33];
    const float* s = src + (long long)blockIdx.z * srcB;
    bf16* dh = hiT + (long long)blockIdx.z * dstB;
    bf16* dl = loT + (long long)blockIdx.z * dstB;
    int c0 = blockIdx.x * 32, r0 = blockIdx.y * 32;
    int tx = threadIdx.x & 31, ty = threadIdx.x >> 5;
    #pragma unroll
    for (int i = 0; i < 32; i += 8)
        t[ty + i][tx] = s[(long long)(r0 + ty + i) * lds + c0 + tx];
    __syncthreads();
    #pragma unroll
    for (int i = 0; i < 32; i += 8) {
        float v = t[tx][ty + i];
        bf16 h, l; split2(v, h, l);
        long long o = (long long)(c0 + ty + i) * ldd + r0 + tx;
        dh[o] = h; dl[o] = l;
    }
}

// ================= bf16-split tensor-core GEMM, cp.async double-buffered =================
// C[M,N] = sum_k A[m,k]*B[n,k]   (both K-major, hi+lo split operands)
// CTA 128x64, BK=32, 256 thr, 8 warps (4M x 2N), warp 32x32.
// OUTS==0: write fp32 C.  OUTS==1: write split bf16 (Chi, Clo).
#define SPAD 40
#define AS_HALVES (128 * SPAD)          // 5120
#define BS_HALVES (64 * SPAD)           // 2560
#define STAGE_HALVES (2*AS_HALVES + 2*BS_HALVES)   // 15360
#define SMEM_BYTES (2 * STAGE_HALVES * 2)          // 61440

__device__ __forceinline__ void cpa16(uint32_t dst, const void* src) {
    asm volatile("cp.async.cg.shared.global [%0], [%1], 16;\n" :: "r"(dst), "l"(src));
}

template<int OUTS>
__global__ void __launch_bounds__(256) gemm_bf16s(
    const bf16* __restrict__ Ahi, const bf16* __restrict__ Alo,
    const bf16* __restrict__ Bhi, const bf16* __restrict__ Blo,
    float* __restrict__ Cf, bf16* __restrict__ Chi, bf16* __restrict__ Clo,
    int M, int N, int K, int lda, int ldb, int ldc,
    int nInner, long long aOut, long long aIn, long long bOut, long long bIn,
    long long cOut, long long cIn)
{
    extern __shared__ bf16 smem[];

    const int z = blockIdx.z;
    const int zo = z / nInner, zi = z - zo * nInner;
    const long long aoff = zo * aOut + zi * aIn;
    const long long boff = zo * bOut + zi * bIn;
    const long long coff = zo * cOut + zi * cIn;

    const int tid = threadIdx.x;
    const int m0 = blockIdx.y << 7;
    const int n0 = blockIdx.x << 6;
    const int wid = tid >> 5, lane = tid & 31;
    const int wm = (wid & 3) * 32;
    const int wn = (wid >> 2) * 32;

    float acc[2][4][4];
    #pragma unroll
    for (int a = 0; a < 2; a++)
        #pragma unroll
        for (int b = 0; b < 4; b++)
            #pragma unroll
            for (int c = 0; c < 4; c++) acc[a][b][c] = 0.f;

    // smem base (shared-state-space address)
    const uint32_t smem_u = (uint32_t)__cvta_generic_to_shared(smem);
    // stage s, section offsets in halves:
    //   A_hi: s*STAGE + 0        A_lo: + AS_HALVES
    //   B_hi: + 2*AS_HALVES      B_lo: + 2*AS_HALVES + BS_HALVES

    // ---- load geometry: 16B (8-half) chunks ----
    const int cw = tid & 3;            // chunk-in-row: cols [cw*8, cw*8+8)
    const int lrow = tid >> 2;         // 0..63

    // ---- ldmatrix lane geometry ----
    const int g = lane >> 3, lr = lane & 7;
    const int a_row = (g & 1) * 8 + lr, a_kc = (g >> 1) * 8;
    const int b_row = (g >> 1) * 8 + lr, b_kc = (g & 1) * 8;

    const int nk = K >> 5;

    // prologue: stage 0 loads for kt=0
    {
        uint32_t sb = smem_u;
        #pragma unroll
        for (int i = 0; i < 2; i++) {
            int r = lrow + i * 64;
            long long go = aoff + (long long)(m0 + r) * lda + cw * 8;
            cpa16(sb + (uint32_t)(r * SPAD + cw * 8) * 2, Ahi + go);
            cpa16(sb + (uint32_t)(AS_HALVES + r * SPAD + cw * 8) * 2, Alo + go);
        }
        {
            long long go = boff + (long long)(n0 + lrow) * ldb + cw * 8;
            cpa16(sb + (uint32_t)(2*AS_HALVES + lrow * SPAD + cw * 8) * 2, Bhi + go);
            cpa16(sb + (uint32_t)(2*AS_HALVES + BS_HALVES + lrow * SPAD + cw * 8) * 2, Blo + go);
        }
        asm volatile("cp.async.commit_group;\n" ::);
    }

    for (int t = 0; t < nk; t++) {
        if (t + 1 < nk) {
            const int kt = (t + 1) << 5;
            uint32_t sb = smem_u + (uint32_t)(((t + 1) & 1) * STAGE_HALVES) * 2;
            #pragma unroll
            for (int i = 0; i < 2; i++) {
                int r = lrow + i * 64;
                long long go = aoff + (long long)(m0 + r) * lda + kt + cw * 8;
                cpa16(sb + (uint32_t)(r * SPAD + cw * 8) * 2, Ahi + go);
                cpa16(sb + (uint32_t)(AS_HALVES + r * SPAD + cw * 8) * 2, Alo + go);
            }
            {
                long long go = boff + (long long)(n0 + lrow) * ldb + kt + cw * 8;
                cpa16(sb + (uint32_t)(2*AS_HALVES + lrow * SPAD + cw * 8) * 2, Bhi + go);
                cpa16(sb + (uint32_t)(2*AS_HALVES + BS_HALVES + lrow * SPAD + cw * 8) * 2, Blo + go);
            }
            asm volatile("cp.async.commit_group;\n" ::);
            asm volatile("cp.async.wait_group 1;\n" ::);
        } else {
            asm volatile("cp.async.wait_group 0;\n" ::);
        }
        __syncthreads();

        const uint32_t sA0 = smem_u + (uint32_t)((t & 1) * STAGE_HALVES) * 2;
        const uint32_t sA1 = sA0 + (uint32_t)AS_HALVES * 2;
        const uint32_t sB0 = sA0 + (uint32_t)(2*AS_HALVES) * 2;
        const uint32_t sB1 = sB0 + (uint32_t)BS_HALVES * 2;

        #pragma unroll
        for (int kk = 0; kk < 2; kk++) {
            uint32_t afr[2][2][4];   // [mi][hi/lo][4]
            #pragma unroll
            for (int mi = 0; mi < 2; mi++) {
                uint32_t off = (uint32_t)((wm + mi * 16 + a_row) * SPAD + kk * 16 + a_kc) * 2;
                asm volatile("ldmatrix.sync.aligned.m8n8.x4.shared.b16 {%0,%1,%2,%3},[%4];"
                    : "=r"(afr[mi][0][0]), "=r"(afr[mi][0][1]), "=r"(afr[mi][0][2]), "=r"(afr[mi][0][3])
                    : "r"(sA0 + off));
                asm volatile("ldmatrix.sync.aligned.m8n8.x4.shared.b16 {%0,%1,%2,%3},[%4];"
                    : "=r"(afr[mi][1][0]), "=r"(afr[mi][1][1]), "=r"(afr[mi][1][2]), "=r"(afr[mi][1][3])
                    : "r"(sA1 + off));
            }
            uint32_t bfr[2][4][2];   // [hi/lo][ni][2]
            #pragma unroll
            for (int j = 0; j < 2; j++) {
                uint32_t off = (uint32_t)((wn + j * 16 + b_row) * SPAD + kk * 16 + b_kc) * 2;
                uint32_t r0, r1, r2, r3;
                asm volatile("ldmatrix.sync.aligned.m8n8.x4.shared.b16 {%0,%1,%2,%3},[%4];"
                    : "=r"(r0), "=r"(r1), "=r"(r2), "=r"(r3) : "r"(sB0 + off));
                bfr[0][j*2][0] = r0; bfr[0][j*2][1] = r1;
                bfr[0][j*2+1][0] = r2; bfr[0][j*2+1][1] = r3;
                asm volatile("ldmatrix.sync.aligned.m8n8.x4.shared.b16 {%0,%1,%2,%3},[%4];"
                    : "=r"(r0), "=r"(r1), "=r"(r2), "=r"(r3) : "r"(sB1 + off));
                bfr[1][j*2][0] = r0; bfr[1][j*2][1] = r1;
                bfr[1][j*2+1][0] = r2; bfr[1][j*2+1][1] = r3;
            }
            #pragma unroll
            for (int mi = 0; mi < 2; mi++)
                #pragma unroll
                for (int ni = 0; ni < 4; ni++) {
                    float* c = acc[mi][ni];
                    #define MMA_ONE(A_, B_) \
                        asm volatile("mma.sync.aligned.m16n8k16.row.col.f32.bf16.bf16.f32 " \
                            "{%0,%1,%2,%3},{%4,%5,%6,%7},{%8,%9},{%0,%1,%2,%3};" \
                            : "+f"(c[0]), "+f"(c[1]), "+f"(c[2]), "+f"(c[3]) \
                            : "r"((A_)[0]), "r"((A_)[1]), "r"((A_)[2]), "r"((A_)[3]), \
                              "r"((B_)[0]), "r"((B_)[1]))
                    MMA_ONE(afr[mi][0], bfr[0][ni]);   // hi*hi
                    MMA_ONE(afr[mi][0], bfr[1][ni]);   // hi*lo
                    MMA_ONE(afr[mi][1], bfr[0][ni]);   // lo*hi
                    #undef MMA_ONE
                }
        }
        __syncthreads();
    }

    // epilogue
    const int er = lane >> 2, ec = (lane & 3) * 2;
    #pragma unroll
    for (int mi = 0; mi < 2; mi++)
        #pragma unroll
        for (int ni = 0; ni < 4; ni++) {
            long long base = coff + (long long)(m0 + wm + mi * 16 + er) * ldc + n0 + wn + ni * 8 + ec;
            long long base2 = base + (long long)8 * ldc;
            float v0 = acc[mi][ni][0], v1 = acc[mi][ni][1];
            float v2 = acc[mi][ni][2], v3 = acc[mi][ni][3];
            if (OUTS == 0) {
                Cf[base] = v0; Cf[base + 1] = v1;
                Cf[base2] = v2; Cf[base2 + 1] = v3;
            } else {
                bf16 h, l;
                split2(v0, h, l); Chi[base] = h;      Clo[base] = l;
                split2(v1, h, l); Chi[base + 1] = h;  Clo[base + 1] = l;
                split2(v2, h, l); Chi[base2] = h;     Clo[base2] = l;
                split2(v3, h, l); Chi[base2 + 1] = h; Clo[base2 + 1] = l;
            }
        }
}

// ================= fused elementwise kernels =================
__global__ void __launch_bounds__(256) rms_q_kernel(const float* __restrict__ qa,
                                                    const float* __restrict__ w,
                                                    bf16* __restrict__ oh, bf16* __restrict__ ol)
{
    const int row = blockIdx.x;
    const float* p = qa + (long long)row * QLORA;
    float v[6]; float ss = 0.f;
    #pragma unroll
    for (int i = 0; i < 6; i++) { v[i] = p[threadIdx.x + i * 256]; ss += v[i] * v[i]; }
    ss = blockSum(ss);
    const float r = rsqrtf(ss / (float)QLORA + 1e-6f);
    #pragma unroll
    for (int i = 0; i < 6; i++) {
        int idx = threadIdx.x + i * 256;
        bf16 h, l; split2(v[i] * r * w[idx], h, l);
        long long o = (long long)row * QLORA + idx;
        oh[o] = h; ol[o] = l;
    }
}

__global__ void __launch_bounds__(256) rms_rope_kv_kernel(float* __restrict__ Kc,
                                                          const float* __restrict__ w,
                                                          const float* __restrict__ freqs,
                                                          bf16* __restrict__ oh, bf16* __restrict__ ol)
{
    const int row = blockIdx.x;
    const int t = row & (SS - 1);
    float* p = Kc + (long long)row * CDIM;
    float v[2]; float ss = 0.f;
    #pragma unroll
    for (int i = 0; i < 2; i++) { v[i] = p[threadIdx.x + i * 256]; ss += v[i] * v[i]; }
    ss = blockSum(ss);
    const float r = rsqrtf(ss / (float)KVLORA + 1e-6f);
    #pragma unroll
    for (int i = 0; i < 2; i++) {
        int idx = threadIdx.x + i * 256;
        float nv = v[i] * r * w[idx];
        p[idx] = nv;
        bf16 h, l; split2(nv, h, l);
        long long o = (long long)row * CDIM + idx;
        oh[o] = h; ol[o] = l;
    }
    if (threadIdx.x < 32) {
        int j = threadIdx.x;
        float c = freqs[t * 64 + 2 * j], s = freqs[t * 64 + 2 * j + 1];
        float e = p[KVLORA + 2 * j], o = p[KVLORA + 2 * j + 1];
        float oe = e * c - o * s, oo = e * s + o * c;
        p[KVLORA + 2 * j] = oe; p[KVLORA + 2 * j + 1] = oo;
        bf16 h, l;
        long long b = (long long)row * CDIM + KVLORA + 2 * j;
        split2(oe, h, l); oh[b] = h;     ol[b] = l;
        split2(oo, h, l); oh[b + 1] = h; ol[b + 1] = l;
    }
}

__global__ void __launch_bounds__(256) rope_q_kernel(const bf16* __restrict__ qh,
                                                     const bf16* __restrict__ ql,
                                                     bf16* __restrict__ Qh, bf16* __restrict__ Ql,
                                                     const float* __restrict__ freqs)
{
    long long idx = (long long)blockIdx.x * 256 + threadIdx.x;
    if (idx >= (long long)MTOT * HH * 32) return;
    int j = idx & 31;
    int h = (idx >> 5) & (HH - 1);
    int m = (int)(idx >> 10);
    int t = m & (SS - 1);
    float c = freqs[t * 64 + 2 * j], s = freqs[t * 64 + 2 * j + 1];
    long long qb = (long long)m * (HH * QK_HEAD) + h * QK_HEAD + NOPE + 2 * j;
    float e = joinv(qh[qb], ql[qb]);
    float o = joinv(qh[qb + 1], ql[qb + 1]);
    long long d = (long long)m * (HH * CDIM) + h * CDIM + KVLORA + 2 * j;
    bf16 hh, ll;
    split2(e * c - o * s, hh, ll); Qh[d] = hh;     Ql[d] = ll;
    split2(e * s + o * c, hh, ll); Qh[d + 1] = hh; Ql[d + 1] = ll;
}

__global__ void __launch_bounds__(256) softmax_kernel(const float* __restrict__ sc,
                                                      const float* __restrict__ mask,
                                                      bf16* __restrict__ ph, bf16* __restrict__ pl)
{
    const long long row = blockIdx.x;
    const int s = (int)(row & (SS - 1));
    const float* p = sc + row * SS;
    const float* mrow = mask + (long long)s * SS;
    float v[4];
    float mx = -INFINITY;
    #pragma unroll
    for (int i = 0; i < 4; i++) {
        int t = threadIdx.x + i * 256;
        v[i] = p[t] * SCALE_F + mrow[t];
        mx = fmaxf(mx, v[i]);
    }
    mx = blockMax(mx);
    float sum = 0.f;
    #pragma unroll
    for (int i = 0; i < 4; i++) { v[i] = __expf(v[i] - mx); sum += v[i]; }
    sum = blockSum(sum);
    const float inv = 1.f / sum;
    #pragma unroll
    for (int i = 0; i < 4; i++) {
        int t = threadIdx.x + i * 256;
        bf16 h, l; split2(v[i] * inv, h, l);
        ph[row * SS + t] = h; pl[row * SS + t] = l;
    }
}

// ---------------- launch ----------------
extern "C" void kernel_launch(void* const* d_in, const int* in_sizes, int n_in,
                              void* d_out, int out_size)
{
    const float* x     = (const float*)d_in[0];
    const float* freqs = (const float*)d_in[1];
    const float* mask  = (const float*)d_in[2];
    const float* wq_a  = (const float*)d_in[3];
    const float* qnw   = (const float*)d_in[4];
    const float* wq_b  = (const float*)d_in[5];
    const float* wkv_a = (const float*)d_in[6];
    const float* kvnw  = (const float*)d_in[7];
    const float* wkv_b = (const float*)d_in[8];
    const float* wo    = (const float*)d_in[9];
    float* out = (float*)d_out;

    static bool attrDone = false;
    if (!attrDone) {
        cudaFuncSetAttribute(gemm_bf16s<0>, cudaFuncAttributeMaxDynamicSharedMemorySize, SMEM_BYTES);
        cudaFuncSetAttribute(gemm_bf16s<1>, cudaFuncAttributeMaxDynamicSharedMemorySize, SMEM_BYTES);
        attrDone = true;
    }

    float *qa, *Kc, *sc;
    cudaGetSymbolAddress((void**)&qa, g_qa);
    cudaGetSymbolAddress((void**)&Kc, g_Kc);
    cudaGetSymbolAddress((void**)&sc, g_sc);

    bf16 *xh,*xl,*wqaTh,*wqaTl,*wkvaTh,*wkvaTl,*qah,*qal,*wqbTh,*wqbTl,*qh,*ql;
    bf16 *wb1h,*wb1l,*Qch,*Qcl,*Kch,*Kcl,*KcTh,*KcTl,*prh,*prl,*o1h,*o1l;
    bf16 *wkvbh,*wkvbl,*o2h,*o2l,*woTh,*woTl;
    cudaGetSymbolAddress((void**)&xh, g_xh);       cudaGetSymbolAddress((void**)&xl, g_xl);
    cudaGetSymbolAddress((void**)&wqaTh, g_wqaTh); cudaGetSymbolAddress((void**)&wqaTl, g_wqaTl);
    cudaGetSymbolAddress((void**)&wkvaTh, g_wkvaTh); cudaGetSymbolAddress((void**)&wkvaTl, g_wkvaTl);
    cudaGetSymbolAddress((void**)&qah, g_qah);     cudaGetSymbolAddress((void**)&qal, g_qal);
    cudaGetSymbolAddress((void**)&wqbTh, g_wqbTh); cudaGetSymbolAddress((void**)&wqbTl, g_wqbTl);
    cudaGetSymbolAddress((void**)&qh, g_qh);       cudaGetSymbolAddress((void**)&ql, g_ql);
    cudaGetSymbolAddress((void**)&wb1h, g_wb1h);   cudaGetSymbolAddress((void**)&wb1l, g_wb1l);
    cudaGetSymbolAddress((void**)&Qch, g_Qch);     cudaGetSymbolAddress((void**)&Qcl, g_Qcl);
    cudaGetSymbolAddress((void**)&Kch, g_Kch);     cudaGetSymbolAddress((void**)&Kcl, g_Kcl);
    cudaGetSymbolAddress((void**)&KcTh, g_KcTh);   cudaGetSymbolAddress((void**)&KcTl, g_KcTl);
    cudaGetSymbolAddress((void**)&prh, g_prh);     cudaGetSymbolAddress((void**)&prl, g_prl);
    cudaGetSymbolAddress((void**)&o1h, g_o1h);     cudaGetSymbolAddress((void**)&o1l, g_o1l);
    cudaGetSymbolAddress((void**)&wkvbh, g_wkvbh); cudaGetSymbolAddress((void**)&wkvbl, g_wkvbl);
    cudaGetSymbolAddress((void**)&o2h, g_o2h);     cudaGetSymbolAddress((void**)&o2l, g_o2l);
    cudaGetSymbolAddress((void**)&woTh, g_woTh);   cudaGetSymbolAddress((void**)&woTl, g_woTl);

    // ---- operand preparation: split + (transposed) split ----
    splitf<<<(MTOT*(long long)DIM + 255)/256, 256>>>(x, xh, xl, (long long)MTOT*DIM);
    splitf<<<(HH*(NOPE+VD)*(long long)KVLORA + 255)/256, 256>>>(wkv_b, wkvbh, wkvbl,
                                                                (long long)HH*(NOPE+VD)*KVLORA);
    splitTf<<<dim3(QLORA/32, DIM/32, 1), 256>>>(wq_a, wqaTh, wqaTl, QLORA, QLORA, DIM, 0, 0);
    splitTf<<<dim3(CDIM/32, DIM/32, 1), 256>>>(wkv_a, wkvaTh, wkvaTl, CDIM, CDIM, DIM, 0, 0);
    splitTf<<<dim3(HH*QK_HEAD/32, QLORA/32, 1), 256>>>(wq_b, wqbTh, wqbTl,
                                                       HH*QK_HEAD, HH*QK_HEAD, QLORA, 0, 0);
    splitTf<<<dim3(DIM/32, DIM/32, 1), 256>>>(wo, woTh, woTl, DIM, DIM, DIM, 0, 0);
    splitTf<<<dim3(KVLORA/32, NOPE/32, HH), 256>>>(wkv_b, wb1h, wb1l,
        KVLORA, KVLORA, NOPE, (long long)(NOPE+VD)*KVLORA, (long long)KVLORA*NOPE);

    // 1. qa = x @ wq_a  (fp32 out)
    gemm_bf16s<0><<<dim3(QLORA/64, MTOT/128, 1), 256, SMEM_BYTES>>>(
        xh, xl, wqaTh, wqaTl, qa, nullptr, nullptr,
        MTOT, QLORA, DIM, DIM, DIM, QLORA, 1, 0, 0, 0, 0, 0, 0);

    // 2. Kc_raw = x @ wkv_a  (fp32 out)
    gemm_bf16s<0><<<dim3(CDIM/64, MTOT/128, 1), 256, SMEM_BYTES>>>(
        xh, xl, wkvaTh, wkvaTl, Kc, nullptr, nullptr,
        MTOT, CDIM, DIM, DIM, DIM, CDIM, 1, 0, 0, 0, 0, 0, 0);

    // 3. rmsnorm qa -> split
    rms_q_kernel<<<MTOT, 256>>>(qa, qnw, qah, qal);

    // 4. kv rms + rope k_pe
    rms_rope_kv_kernel<<<MTOT, 256>>>(Kc, kvnw, freqs, Kch, Kcl);

    // 4b. KcT (per batch)
    splitTf<<<dim3(KVLORA/32, SS/32, BB), 256>>>(Kc, KcTh, KcTl,
        KVLORA, CDIM, SS, (long long)SS*CDIM, (long long)KVLORA*SS);

    // 5. q = qa_n @ wq_b  (split out)
    gemm_bf16s<1><<<dim3(HH*QK_HEAD/64, MTOT/128, 1), 256, SMEM_BYTES>>>(
        qah, qal, wqbTh, wqbTl, nullptr, qh, ql,
        MTOT, HH*QK_HEAD, QLORA, QLORA, QLORA, HH*QK_HEAD, 1, 0, 0, 0, 0, 0, 0);

    // 6. rope q_pe -> Qc[...,512:576] (split)
    rope_q_kernel<<<(MTOT*HH*32)/256, 256>>>(qh, ql, Qch, Qcl, freqs);

    // 7. q_abs per head (split out), z=h
    gemm_bf16s<1><<<dim3(KVLORA/64, MTOT/128, HH), 256, SMEM_BYTES>>>(
        qh, ql, wb1h, wb1l, nullptr, Qch, Qcl,
        MTOT, KVLORA, NOPE, HH*QK_HEAD, NOPE, HH*CDIM,
        1, QK_HEAD, 0, (long long)KVLORA*NOPE, 0, CDIM, 0);

    // 8. scores per (b,h) (fp32 out), z=b*H+h
    gemm_bf16s<0><<<dim3(SS/64, SS/128, BB*HH), 256, SMEM_BYTES>>>(
        Qch, Qcl, Kch, Kcl, sc, nullptr, nullptr,
        SS, SS, CDIM, HH*CDIM, CDIM, SS,
        HH,
        (long long)SS*HH*CDIM, CDIM,
        (long long)SS*CDIM, 0,
        (long long)HH*SS*SS, (long long)SS*SS);

    // 9. softmax -> split probs
    softmax_kernel<<<BB*HH*SS, 256>>>(sc, mask, prh, prl);

    // 10. o1 = probs @ kv_n  (split out), z=b*H+h
    gemm_bf16s<1><<<dim3(KVLORA/64, SS/128, BB*HH), 256, SMEM_BYTES>>>(
        prh, prl, KcTh, KcTl, nullptr, o1h, o1l,
        SS, KVLORA, SS, SS, SS, HH*KVLORA,
        HH,
        (long long)HH*SS*SS, (long long)SS*SS,
        (long long)KVLORA*SS, 0,
        (long long)SS*HH*KVLORA, (long long)KVLORA);

    // 11. o2 = o1 @ wkv_b[h,128:,:]^T  (split out), z=h
    gemm_bf16s<1><<<dim3(VD/64, MTOT/128, HH), 256, SMEM_BYTES>>>(
        o1h, o1l, wkvbh + (long long)NOPE*KVLORA, wkvbl + (long long)NOPE*KVLORA,
        nullptr, o2h, o2l,
        MTOT, VD, KVLORA, HH*KVLORA, KVLORA, DIM,
        1, (long long)KVLORA, 0,
        (long long)(NOPE+VD)*KVLORA, 0,
        (long long)VD, 0);

    // 12. out = o2 @ wo  (fp32 out)
    gemm_bf16s<0><<<dim3(DIM/64, MTOT/128, 1), 256, SMEM_BYTES>>>(
        o2h, o2l, woTh, woTl, out, nullptr, nullptr,
        MTOT, DIM, DIM, DIM, DIM, DIM, 1, 0, 0, 0, 0, 0, 0);
}